// round 1
// baseline (speedup 1.0000x reference)
#include <cuda_runtime.h>
#include <cuda_bf16.h>
#include <math.h>

// Problem constants
#define BB 2
#define SS 2048
#define DD 1024
#define HH 16
#define HD 64
#define NF 16
#define FFN 4096
#define MM (BB*SS)          // 4096 rows
#define EPS_RMS 1.1920929e-07f

// ---------------- scratch (device globals; allocation-free) ----------------
static __device__ float g_xn   [MM*DD];        // 16 MB
static __device__ float g_qkv  [MM*3*DD];      // 48 MB
static __device__ float g_o    [MM*DD];        // 16 MB
static __device__ float g_oproj[MM*DD];        // 16 MB
static __device__ float g_gl   [MM*DD];        // 16 MB
static __device__ float g_x    [MM*DD];        // 16 MB
static __device__ float g_x12  [MM*2*FFN];     // 128 MB
static __device__ float g_ffnin[MM*FFN];       // 64 MB
static __device__ float g_Q    [HD*HD];        // Householder product

// ---------------- rmsnorm ----------------
__global__ void rmsnorm_k(const float* __restrict__ x, float* __restrict__ y) {
    int row = blockIdx.x;
    const float* xr = x + (size_t)row * DD;
    float* yr = y + (size_t)row * DD;
    __shared__ float red[256];
    int tid = threadIdx.x;
    float s = 0.f;
    #pragma unroll
    for (int i = tid; i < DD; i += 256) { float v = xr[i]; s += v * v; }
    red[tid] = s; __syncthreads();
    for (int off = 128; off > 0; off >>= 1) {
        if (tid < off) red[tid] += red[tid + off];
        __syncthreads();
    }
    float r = rsqrtf(red[0] / (float)DD + EPS_RMS);
    for (int i = tid; i < DD; i += 256) yr[i] = xr[i] * r;
}

// ---------------- Householder product Q = H_31 ... H_0 ----------------
__global__ void hh_k(const float* __restrict__ vs, float* __restrict__ Qout) {
    __shared__ float Q[HD][HD];
    __shared__ float v[HD];
    __shared__ float w[HD];
    __shared__ float cs;
    int tid = threadIdx.x;
    for (int idx = tid; idx < HD*HD; idx += 256)
        Q[idx / HD][idx % HD] = (idx / HD == idx % HD) ? 1.f : 0.f;
    __syncthreads();
    for (int r = 0; r < HD/2; r++) {
        if (tid < HD) v[tid] = vs[r*HD + tid];
        __syncthreads();
        if (tid == 0) {
            float n = 0.f;
            for (int i = 0; i < HD; i++) n += v[i]*v[i];
            cs = 2.f / (n + 1e-8f);
        }
        __syncthreads();
        if (tid < HD) {
            float s = 0.f;
            for (int i = 0; i < HD; i++) s += v[i] * Q[i][tid];
            w[tid] = s;
        }
        __syncthreads();
        for (int idx = tid; idx < HD*HD; idx += 256) {
            int i = idx / HD, j = idx % HD;
            Q[i][j] -= cs * v[i] * w[j];
        }
        __syncthreads();
    }
    for (int idx = tid; idx < HD*HD; idx += 256)
        Qout[idx] = Q[idx / HD][idx % HD];
}

// ---------------- q,k -> rot(q @ Q^T) @ Q in-place ----------------
__global__ void qk_rope_k(float* __restrict__ qkv, const float* __restrict__ Qm,
                          const float* __restrict__ inv_freq,
                          const float* __restrict__ rope_pos) {
    int bs = blockIdx.x;          // 0..MM-1
    int s  = bs % SS;
    int tid = threadIdx.x;
    __shared__ float Qs[HD*HD];
    __shared__ float buf[4][HD];
    __shared__ float t1s[4][HD];
    for (int idx = tid; idx < HD*HD; idx += 256) Qs[idx] = Qm[idx];
    int hh = tid >> 6;            // 0..3 sub-head
    int d  = tid & 63;
    float pos = rope_pos[2*s];
    float ang = pos * inv_freq[d & 15];
    float ca = cosf(ang), sa = sinf(ang);
    __syncthreads();
    for (int part = 0; part < 2; part++) {       // q then k
        float* base = qkv + (size_t)bs * (3*DD) + part * DD;
        for (int hg = 0; hg < 4; hg++) {
            int h = hg * 4 + hh;
            float* rowp = base + h * HD;
            buf[hh][d] = rowp[d];
            __syncthreads();
            float t1 = 0.f;                      // (q @ Q^T)[d]
            #pragma unroll
            for (int e = 0; e < HD; e++) t1 += buf[hh][e] * Qs[d*HD + e];
            t1s[hh][d] = t1;
            __syncthreads();
            float partner = (d < 32) ? -t1s[hh][d + 32] : t1s[hh][d - 32];
            float rv = t1 * ca + partner * sa;   // rope
            __syncthreads();
            buf[hh][d] = rv;
            __syncthreads();
            float o = 0.f;                       // (rv @ Q)[d]
            #pragma unroll
            for (int e = 0; e < HD; e++) o += buf[hh][e] * Qs[e*HD + d];
            rowp[d] = o;
            __syncthreads();
        }
    }
}

// ---------------- causal attention, online softmax ----------------
__global__ void attn_k(const float* __restrict__ qkv, float* __restrict__ o) {
    int row = blockIdx.x;                 // ((b*H)+h)*S + s
    int s = row % SS;
    int h = (row / SS) % HH;
    int b = row / (SS * HH);
    int tid = threadIdx.x;
    const float* qr = qkv + ((size_t)(b*SS + s)) * (3*DD) + h*HD;
    __shared__ float qs[HD];
    __shared__ float ps[256];
    __shared__ float red[256];
    __shared__ float acc[HD];
    __shared__ float part[4][HD];
    __shared__ float m_s, l_s, scale_s, newm_s;
    if (tid < HD) { qs[tid] = qr[tid]; acc[tid] = 0.f; }
    if (tid == 0) { m_s = -1e30f; l_s = 0.f; }
    __syncthreads();
    for (int t0 = 0; t0 <= s; t0 += 256) {
        int nt = min(256, s + 1 - t0);
        float sc = -1e30f;
        if (tid < nt) {
            const float* kr = qkv + ((size_t)(b*SS + t0 + tid)) * (3*DD) + DD + h*HD;
            float a0 = 0.f;
            #pragma unroll
            for (int e = 0; e < HD; e++) a0 += qs[e] * kr[e];
            sc = a0 * 0.125f;                 // 1/sqrt(64)
        }
        ps[tid] = sc; red[tid] = sc;
        __syncthreads();
        for (int off = 128; off > 0; off >>= 1) {
            if (tid < off) red[tid] = fmaxf(red[tid], red[tid + off]);
            __syncthreads();
        }
        if (tid == 0) {
            float nm = fmaxf(m_s, red[0]);
            scale_s = __expf(m_s - nm) == 0.f && m_s <= -1e29f ? 0.f : expf(m_s - nm);
            newm_s = nm;
        }
        __syncthreads();
        float nm = newm_s;
        float p = (tid < nt) ? expf(ps[tid] - nm) : 0.f;
        ps[tid] = p; red[tid] = p;
        __syncthreads();
        for (int off = 128; off > 0; off >>= 1) {
            if (tid < off) red[tid] += red[tid + off];
            __syncthreads();
        }
        if (tid == 0) { l_s = l_s * scale_s + red[0]; m_s = newm_s; }
        // P@V, split across 4 groups of 64 threads
        int g = tid >> 6, d = tid & 63;
        float pa = 0.f;
        int i0 = g * 64, i1 = min(i0 + 64, nt);
        for (int i = i0; i < i1; i++) {
            const float* vr = qkv + ((size_t)(b*SS + t0 + i)) * (3*DD) + 2*DD + h*HD;
            pa += ps[i] * vr[d];
        }
        part[g][d] = pa;
        __syncthreads();
        if (tid < HD)
            acc[tid] = acc[tid] * scale_s + part[0][tid] + part[1][tid] + part[2][tid] + part[3][tid];
        __syncthreads();
    }
    if (tid < HD)
        o[((size_t)(b*SS + s)) * DD + h*HD + tid] = acc[tid] / l_s;
}

// ---------------- SGEMM: C[M,N] = A[M,K] @ W[N,K]^T (+bias)(+resid) ----------------
__global__ void sgemm_k(const float* __restrict__ A, const float* __restrict__ W,
                        float* __restrict__ C, int M, int N, int K,
                        const float* __restrict__ bias, const float* __restrict__ resid) {
    __shared__ __align__(16) float As[16][64];
    __shared__ __align__(16) float Ws[16][64];
    int tid = threadIdx.x;
    int tx = tid & 15, ty = tid >> 4;
    int m0 = blockIdx.y * 64, n0 = blockIdx.x * 64;
    int lr = tid >> 2;          // load row 0..63
    int lc = tid & 3;           // float4 col 0..3
    float cr[4][4] = {};
    for (int k0 = 0; k0 < K; k0 += 16) {
        float4 a4 = *reinterpret_cast<const float4*>(A + (size_t)(m0 + lr) * K + k0 + lc * 4);
        float4 w4 = *reinterpret_cast<const float4*>(W + (size_t)(n0 + lr) * K + k0 + lc * 4);
        As[lc*4+0][lr] = a4.x; As[lc*4+1][lr] = a4.y; As[lc*4+2][lr] = a4.z; As[lc*4+3][lr] = a4.w;
        Ws[lc*4+0][lr] = w4.x; Ws[lc*4+1][lr] = w4.y; Ws[lc*4+2][lr] = w4.z; Ws[lc*4+3][lr] = w4.w;
        __syncthreads();
        #pragma unroll
        for (int k = 0; k < 16; k++) {
            float4 a = *reinterpret_cast<const float4*>(&As[k][ty*4]);
            float4 w = *reinterpret_cast<const float4*>(&Ws[k][tx*4]);
            float ar[4] = {a.x, a.y, a.z, a.w};
            float wr[4] = {w.x, w.y, w.z, w.w};
            #pragma unroll
            for (int i = 0; i < 4; i++)
                #pragma unroll
                for (int j = 0; j < 4; j++)
                    cr[i][j] += ar[i] * wr[j];
        }
        __syncthreads();
    }
    #pragma unroll
    for (int i = 0; i < 4; i++) {
        int m = m0 + ty*4 + i;
        #pragma unroll
        for (int j = 0; j < 4; j++) {
            int n = n0 + tx*4 + j;
            float v = cr[i][j];
            if (bias)  v += bias[n];
            if (resid) v += resid[(size_t)m * N + n];
            C[(size_t)m * N + n] = v;
        }
    }
}

// ---------------- elementwise: x = resid + oproj * sigmoid(gl) ----------------
__global__ void gate_res_k(const float* __restrict__ resid, const float* __restrict__ oproj,
                           const float* __restrict__ gl, float* __restrict__ xout, int n) {
    for (int i = blockIdx.x * blockDim.x + threadIdx.x; i < n; i += gridDim.x * blockDim.x) {
        float g = 1.f / (1.f + expf(-gl[i]));
        xout[i] = resid[i] + oproj[i] * g;
    }
}

// ---------------- elementwise: ffnin = silu(x1) * x2 ----------------
__global__ void swiglu_k(const float* __restrict__ x12, float* __restrict__ ffnin, int n) {
    for (int i = blockIdx.x * blockDim.x + threadIdx.x; i < n; i += gridDim.x * blockDim.x) {
        int m = i / FFN, j = i % FFN;
        float a = x12[(size_t)m * (2*FFN) + j];
        float b = x12[(size_t)m * (2*FFN) + FFN + j];
        ffnin[i] = (a / (1.f + expf(-a))) * b;
    }
}

// ---------------- launch ----------------
extern "C" void kernel_launch(void* const* d_in, const int* in_sizes, int n_in,
                              void* d_out, int out_size) {
    const float* x        = (const float*)d_in[0];
    // d_in[1] = mask (causal, implicit) — unused
    const float* qkv_w    = (const float*)d_in[2];
    const float* out_w    = (const float*)d_in[3];
    const float* gate_w   = (const float*)d_in[4];
    const float* gate_b   = (const float*)d_in[5];
    const float* w12      = (const float*)d_in[6];
    const float* w3       = (const float*)d_in[7];
    const float* hh_vs    = (const float*)d_in[8];
    const float* inv_freq = (const float*)d_in[9];
    const float* rope_pos = (const float*)d_in[10];
    float* out = (float*)d_out;

    float *xn, *qkv, *o_, *oproj, *gl, *x_, *x12, *ffnin, *Qm;
    cudaGetSymbolAddress((void**)&xn,    g_xn);
    cudaGetSymbolAddress((void**)&qkv,   g_qkv);
    cudaGetSymbolAddress((void**)&o_,    g_o);
    cudaGetSymbolAddress((void**)&oproj, g_oproj);
    cudaGetSymbolAddress((void**)&gl,    g_gl);
    cudaGetSymbolAddress((void**)&x_,    g_x);
    cudaGetSymbolAddress((void**)&x12,   g_x12);
    cudaGetSymbolAddress((void**)&ffnin, g_ffnin);
    cudaGetSymbolAddress((void**)&Qm,    g_Q);

    // 1. xn = rmsnorm(x)
    rmsnorm_k<<<MM, 256>>>(x, xn);
    // 2. Q = householder product
    hh_k<<<1, 256>>>(hh_vs, Qm);
    // 3. qkv = xn @ qkv_w^T
    sgemm_k<<<dim3((3*DD)/64, MM/64), 256>>>(xn, qkv_w, qkv, MM, 3*DD, DD, nullptr, nullptr);
    // 4. q,k <- rot(q @ Q^T) @ Q
    qk_rope_k<<<MM, 256>>>(qkv, Qm, inv_freq, rope_pos);
    // 5. attention
    attn_k<<<BB*HH*SS, 256>>>(qkv, o_);
    // 6. oproj = o @ out_w^T
    sgemm_k<<<dim3(DD/64, MM/64), 256>>>(o_, out_w, oproj, MM, DD, DD, nullptr, nullptr);
    // 7. gl = oproj @ gate_w^T + gate_b
    sgemm_k<<<dim3(DD/64, MM/64), 256>>>(oproj, gate_w, gl, MM, DD, DD, gate_b, nullptr);
    // 8. x = resid + oproj * sigmoid(gl)
    gate_res_k<<<1024, 256>>>(x, oproj, gl, x_, MM*DD);
    // 9. xn = rmsnorm(x)
    rmsnorm_k<<<MM, 256>>>(x_, xn);
    // 10. x12 = xn @ w12^T
    sgemm_k<<<dim3((2*FFN)/64, MM/64), 256>>>(xn, w12, x12, MM, 2*FFN, DD, nullptr, nullptr);
    // 11. ffnin = silu(x1) * x2
    swiglu_k<<<2048, 256>>>(x12, ffnin, MM*FFN);
    // 12. out = x + ffnin @ w3^T
    sgemm_k<<<dim3(DD/64, MM/64), 256>>>(ffnin, w3, out, MM, DD, FFN, nullptr, x_);
}

// round 2
// speedup vs baseline: 5.1942x; 5.1942x over previous
#include <cuda_runtime.h>
#include <cuda_bf16.h>
#include <math.h>

// Problem constants
#define BB 2
#define SS 2048
#define DD 1024
#define HH 16
#define HD 64
#define FFN 4096
#define MM (BB*SS)          // 4096 rows
#define EPS_RMS 1.1920929e-07f

// ---------------- scratch (device globals; allocation-free) ----------------
static __device__ float g_xn   [MM*DD];
static __device__ float g_qkv  [MM*3*DD];
static __device__ float g_o    [MM*DD];
static __device__ float g_oproj[MM*DD];
static __device__ float g_gl   [MM*DD];
static __device__ float g_x    [MM*DD];
static __device__ float g_x12  [MM*2*FFN];
static __device__ float g_ffnin[MM*FFN];
static __device__ float g_Q    [HD*HD];
static __device__ float g_w    [3*DD*DD];      // folded qkv weights

// ---------------- rmsnorm (1 block / row, one float4 per thread) ----------------
__global__ void rmsnorm_k(const float* __restrict__ x, float* __restrict__ y) {
    int row = blockIdx.x;
    const float4* xr = (const float4*)(x + (size_t)row * DD);
    float4* yr = (float4*)(y + (size_t)row * DD);
    int tid = threadIdx.x;
    float4 v = xr[tid];
    float s = v.x*v.x + v.y*v.y + v.z*v.z + v.w*v.w;
    #pragma unroll
    for (int w = 16; w > 0; w >>= 1) s += __shfl_xor_sync(0xffffffffu, s, w);
    __shared__ float red[8];
    __shared__ float tot;
    if ((tid & 31) == 0) red[tid >> 5] = s;
    __syncthreads();
    if (tid == 0) {
        float t = 0.f;
        #pragma unroll
        for (int i = 0; i < 8; i++) t += red[i];
        tot = t;
    }
    __syncthreads();
    float r = rsqrtf(tot / (float)DD + EPS_RMS);
    float4 o = make_float4(v.x*r, v.y*r, v.z*r, v.w*r);
    yr[tid] = o;
}

// ---------------- Householder product Q = H_31 ... H_0 ----------------
__global__ void hh_k(const float* __restrict__ vs, float* __restrict__ Qout) {
    __shared__ float Q[HD][HD];
    __shared__ float v[HD];
    __shared__ float w[HD];
    __shared__ float cs;
    int tid = threadIdx.x;
    for (int idx = tid; idx < HD*HD; idx += 256)
        Q[idx / HD][idx % HD] = (idx / HD == idx % HD) ? 1.f : 0.f;
    __syncthreads();
    for (int r = 0; r < HD/2; r++) {
        if (tid < HD) v[tid] = vs[r*HD + tid];
        __syncthreads();
        if (tid == 0) {
            float n = 0.f;
            for (int i = 0; i < HD; i++) n += v[i]*v[i];
            cs = 2.f / (n + 1e-8f);
        }
        __syncthreads();
        if (tid < HD) {
            float s = 0.f;
            for (int i = 0; i < HD; i++) s += v[i] * Q[i][tid];
            w[tid] = s;
        }
        __syncthreads();
        for (int idx = tid; idx < HD*HD; idx += 256) {
            int i = idx / HD, j = idx % HD;
            Q[i][j] -= cs * v[i] * w[j];
        }
        __syncthreads();
    }
    for (int idx = tid; idx < HD*HD; idx += 256)
        Qout[idx] = Q[idx / HD][idx % HD];
}

// ---------------- fold Q into q,k weight rows: W'[hd+i,:] = sum_j Q[i][j] W[hd+j,:] ----------------
__global__ void foldw_k(const float* __restrict__ W, const float* __restrict__ Qm,
                        float* __restrict__ Wout) {
    int row = blockIdx.x;       // 0..3071
    int tid = threadIdx.x;      // 256 threads, 4 cols each
    __shared__ float coef[HD];
    bool xform = row < 2*DD;    // q and k rows only
    if (xform && tid < HD) coef[tid] = Qm[(row & 63)*HD + tid];
    __syncthreads();
    float4 acc;
    if (!xform) {
        acc = *(const float4*)(W + (size_t)row*DD + tid*4);
    } else {
        acc = make_float4(0.f, 0.f, 0.f, 0.f);
        int base = row & ~63;
        #pragma unroll 4
        for (int j = 0; j < HD; j++) {
            float cf = coef[j];
            float4 w = *(const float4*)(W + (size_t)(base + j)*DD + tid*4);
            acc.x += cf*w.x; acc.y += cf*w.y; acc.z += cf*w.z; acc.w += cf*w.w;
        }
    }
    *(float4*)(Wout + (size_t)row*DD + tid*4) = acc;
}

// ---------------- elementwise rope on q,k (q also pre-scaled by 1/sqrt(HD)) ----------------
__global__ void rope_k(float* __restrict__ qkv, const float* __restrict__ inv_freq,
                       const float* __restrict__ rope_pos) {
    int idx = blockIdx.x * 256 + threadIdx.x;   // MM*32*32 total
    int dp = idx & 31;            // 0..31 (pair d, d+32)
    int ph = (idx >> 5) & 31;     // part*16 + head
    int bs = idx >> 10;
    int s  = bs & (SS-1);
    float pos = rope_pos[2*s];
    float ang = pos * inv_freq[dp & 15];
    float c, sn;
    sincosf(ang, &sn, &c);
    size_t base = (size_t)bs*(3*DD) + (size_t)(ph>>4)*DD + (size_t)(ph&15)*HD;
    float t1 = qkv[base + dp], t2 = qkv[base + dp + 32];
    float o1 = t1*c - t2*sn;
    float o2 = t2*c + t1*sn;
    if (ph < 16) { o1 *= 0.125f; o2 *= 0.125f; }   // q scaled by 1/sqrt(64)
    qkv[base + dp] = o1;
    qkv[base + dp + 32] = o2;
}

// ---------------- flash attention: 64 queries per block, online softmax ----------------
__global__ void __launch_bounds__(256, 2) flash_k(const float* __restrict__ qkv,
                                                  float* __restrict__ o) {
    extern __shared__ float sm[];
    float* Qs = sm;             // [64][64] xor-swizzled chunks
    float* Ks = sm + 4096;
    float* Vs = sm + 8192;
    float* Ps = sm + 12288;
    int tid = threadIdx.x;
    int tx = tid & 15, ty = tid >> 4;
    int qt = gridDim.x - 1 - blockIdx.x;      // longest tiles first
    int qi0 = qt * 64;
    int b = blockIdx.y >> 4, h = blockIdx.y & 15;

    // load Q tile (swizzled: chunk phys = c4 ^ (row>>2))
    #pragma unroll
    for (int it = 0; it < 4; it++) {
        int idx = tid + it*256;
        int r = idx >> 4, c4 = idx & 15;
        float4 v = *(const float4*)(qkv + ((size_t)(b*SS + qi0 + r))*(3*DD) + h*HD + c4*4);
        float* dst = Qs + r*64 + ((c4 ^ (r >> 2)) << 2);
        dst[0]=v.x; dst[1]=v.y; dst[2]=v.z; dst[3]=v.w;
    }
    float m_i[4], l_i[4], oacc[4][4];
    #pragma unroll
    for (int i = 0; i < 4; i++) {
        m_i[i] = -1e30f; l_i[i] = 0.f;
        #pragma unroll
        for (int j = 0; j < 4; j++) oacc[i][j] = 0.f;
    }

    for (int j0 = 0; j0 <= qi0; j0 += 64) {
        __syncthreads();
        #pragma unroll
        for (int it = 0; it < 4; it++) {
            int idx = tid + it*256;
            int r = idx >> 4, c4 = idx & 15;
            size_t g = ((size_t)(b*SS + j0 + r))*(3*DD) + h*HD + c4*4;
            float4 kv = *(const float4*)(qkv + g + DD);
            float4 vv = *(const float4*)(qkv + g + 2*DD);
            int off = r*64 + ((c4 ^ (r >> 2)) << 2);
            Ks[off+0]=kv.x; Ks[off+1]=kv.y; Ks[off+2]=kv.z; Ks[off+3]=kv.w;
            Vs[off+0]=vv.x; Vs[off+1]=vv.y; Vs[off+2]=vv.z; Vs[off+3]=vv.w;
        }
        __syncthreads();
        // S = Q K^T
        float s[4][4];
        #pragma unroll
        for (int i = 0; i < 4; i++)
            #pragma unroll
            for (int j = 0; j < 4; j++) s[i][j] = 0.f;
        #pragma unroll
        for (int k4 = 0; k4 < 16; k4++) {
            float a[4][4], bf[4][4];
            #pragma unroll
            for (int i = 0; i < 4; i++)
                *(float4*)a[i] = *(const float4*)(Qs + (ty*4+i)*64 + ((k4 ^ ty) << 2));
            #pragma unroll
            for (int j = 0; j < 4; j++)
                *(float4*)bf[j] = *(const float4*)(Ks + (tx*4+j)*64 + ((k4 ^ tx) << 2));
            #pragma unroll
            for (int i = 0; i < 4; i++)
                #pragma unroll
                for (int j = 0; j < 4; j++)
                    #pragma unroll
                    for (int u = 0; u < 4; u++)
                        s[i][j] += a[i][u] * bf[j][u];
        }
        if (j0 == qi0) {   // causal mask on diagonal tile
            #pragma unroll
            for (int i = 0; i < 4; i++)
                #pragma unroll
                for (int j = 0; j < 4; j++)
                    if (tx*4+j > ty*4+i) s[i][j] = -1e30f;
        }
        // online softmax per row (16 lanes own a row)
        #pragma unroll
        for (int i = 0; i < 4; i++) {
            float mx = fmaxf(fmaxf(s[i][0], s[i][1]), fmaxf(s[i][2], s[i][3]));
            #pragma unroll
            for (int w = 1; w < 16; w <<= 1) mx = fmaxf(mx, __shfl_xor_sync(0xffffffffu, mx, w));
            float nm = fmaxf(m_i[i], mx);
            float alpha = __expf(m_i[i] - nm);
            float sum = 0.f;
            #pragma unroll
            for (int j = 0; j < 4; j++) { float p = __expf(s[i][j] - nm); s[i][j] = p; sum += p; }
            #pragma unroll
            for (int w = 1; w < 16; w <<= 1) sum += __shfl_xor_sync(0xffffffffu, sum, w);
            l_i[i] = l_i[i]*alpha + sum;
            m_i[i] = nm;
            #pragma unroll
            for (int j = 0; j < 4; j++) oacc[i][j] *= alpha;
            int r = ty*4 + i;
            int base = r*64 + ((tx ^ ty) << 2);
            Ps[base+0]=s[i][0]; Ps[base+1]=s[i][1]; Ps[base+2]=s[i][2]; Ps[base+3]=s[i][3];
        }
        __syncthreads();
        // O += P @ V
        #pragma unroll
        for (int k4 = 0; k4 < 16; k4++) {
            float p4[4][4], v4[4][4];
            #pragma unroll
            for (int i = 0; i < 4; i++)
                *(float4*)p4[i] = *(const float4*)(Ps + (ty*4+i)*64 + ((k4 ^ ty) << 2));
            #pragma unroll
            for (int u = 0; u < 4; u++)
                *(float4*)v4[u] = *(const float4*)(Vs + (k4*4+u)*64 + ((tx ^ k4) << 2));
            #pragma unroll
            for (int i = 0; i < 4; i++)
                #pragma unroll
                for (int j = 0; j < 4; j++)
                    #pragma unroll
                    for (int u = 0; u < 4; u++)
                        oacc[i][j] += p4[i][u] * v4[u][j];
        }
    }
    // epilogue
    #pragma unroll
    for (int i = 0; i < 4; i++) {
        float inv = 1.f / l_i[i];
        int q = qi0 + ty*4 + i;
        float4 ov = make_float4(oacc[i][0]*inv, oacc[i][1]*inv, oacc[i][2]*inv, oacc[i][3]*inv);
        *(float4*)(o + ((size_t)(b*SS + q))*DD + h*HD + tx*4) = ov;
    }
}

// ---------------- SGEMM 128x128x16, 8x8 per thread: C = A @ W^T (+bias)(+resid) ----------------
__global__ void __launch_bounds__(256, 2) sgemm128_k(
        const float* __restrict__ A, const float* __restrict__ W,
        float* __restrict__ C, int M, int N, int K,
        const float* __restrict__ bias, const float* __restrict__ resid) {
    __shared__ __align__(16) float As[16][132];
    __shared__ __align__(16) float Ws[16][132];
    int tid = threadIdx.x;
    int tx = tid & 15, ty = tid >> 4;
    int m0 = blockIdx.y * 128, n0 = blockIdx.x * 128;
    int lr = tid >> 2, lc = tid & 3;
    float acc[2][2][4][4] = {};
    for (int k0 = 0; k0 < K; k0 += 16) {
        #pragma unroll
        for (int hf = 0; hf < 2; hf++) {
            int r = hf*64 + lr;
            float4 a4 = *(const float4*)(A + (size_t)(m0 + r)*K + k0 + lc*4);
            As[lc*4+0][r]=a4.x; As[lc*4+1][r]=a4.y; As[lc*4+2][r]=a4.z; As[lc*4+3][r]=a4.w;
            float4 w4 = *(const float4*)(W + (size_t)(n0 + r)*K + k0 + lc*4);
            Ws[lc*4+0][r]=w4.x; Ws[lc*4+1][r]=w4.y; Ws[lc*4+2][r]=w4.z; Ws[lc*4+3][r]=w4.w;
        }
        __syncthreads();
        #pragma unroll
        for (int k = 0; k < 16; k++) {
            float ar[2][4], br[2][4];
            *(float4*)ar[0] = *(const float4*)&As[k][ty*4];
            *(float4*)ar[1] = *(const float4*)&As[k][64 + ty*4];
            *(float4*)br[0] = *(const float4*)&Ws[k][tx*4];
            *(float4*)br[1] = *(const float4*)&Ws[k][64 + tx*4];
            #pragma unroll
            for (int ci = 0; ci < 2; ci++)
                #pragma unroll
                for (int i = 0; i < 4; i++)
                    #pragma unroll
                    for (int cj = 0; cj < 2; cj++)
                        #pragma unroll
                        for (int j = 0; j < 4; j++)
                            acc[ci][cj][i][j] += ar[ci][i] * br[cj][j];
        }
        __syncthreads();
    }
    #pragma unroll
    for (int ci = 0; ci < 2; ci++)
        #pragma unroll
        for (int i = 0; i < 4; i++) {
            int m = m0 + ci*64 + ty*4 + i;
            #pragma unroll
            for (int cj = 0; cj < 2; cj++) {
                int n = n0 + cj*64 + tx*4;
                float4 v = make_float4(acc[ci][cj][i][0], acc[ci][cj][i][1],
                                       acc[ci][cj][i][2], acc[ci][cj][i][3]);
                if (bias) {
                    float4 bv = *(const float4*)(bias + n);
                    v.x += bv.x; v.y += bv.y; v.z += bv.z; v.w += bv.w;
                }
                if (resid) {
                    float4 rv = *(const float4*)(resid + (size_t)m*N + n);
                    v.x += rv.x; v.y += rv.y; v.z += rv.z; v.w += rv.w;
                }
                *(float4*)(C + (size_t)m*N + n) = v;
            }
        }
}

// ---------------- x = resid + oproj * sigmoid(gl) ----------------
__global__ void gate_res_k(const float* __restrict__ resid, const float* __restrict__ oproj,
                           const float* __restrict__ gl, float* __restrict__ xout, int n4) {
    int i = blockIdx.x * blockDim.x + threadIdx.x;
    if (i >= n4) return;
    float4 r = ((const float4*)resid)[i];
    float4 p = ((const float4*)oproj)[i];
    float4 g = ((const float4*)gl)[i];
    float4 o;
    o.x = r.x + p.x / (1.f + __expf(-g.x));
    o.y = r.y + p.y / (1.f + __expf(-g.y));
    o.z = r.z + p.z / (1.f + __expf(-g.z));
    o.w = r.w + p.w / (1.f + __expf(-g.w));
    ((float4*)xout)[i] = o;
}

// ---------------- ffnin = silu(x1) * x2 ----------------
__global__ void swiglu_k(const float* __restrict__ x12, float* __restrict__ ffnin, int n4) {
    int i = blockIdx.x * blockDim.x + threadIdx.x;
    if (i >= n4) return;
    int m = i >> 10;              // FFN/4 = 1024 float4 per row
    int j4 = i & 1023;
    float4 a = ((const float4*)x12)[(size_t)m*2048 + j4];
    float4 b = ((const float4*)x12)[(size_t)m*2048 + 1024 + j4];
    float4 o;
    o.x = (a.x / (1.f + __expf(-a.x))) * b.x;
    o.y = (a.y / (1.f + __expf(-a.y))) * b.y;
    o.z = (a.z / (1.f + __expf(-a.z))) * b.z;
    o.w = (a.w / (1.f + __expf(-a.w))) * b.w;
    ((float4*)ffnin)[i] = o;
}

// ---------------- launch ----------------
extern "C" void kernel_launch(void* const* d_in, const int* in_sizes, int n_in,
                              void* d_out, int out_size) {
    const float* x        = (const float*)d_in[0];
    const float* qkv_w    = (const float*)d_in[2];
    const float* out_w    = (const float*)d_in[3];
    const float* gate_w   = (const float*)d_in[4];
    const float* gate_b   = (const float*)d_in[5];
    const float* w12      = (const float*)d_in[6];
    const float* w3       = (const float*)d_in[7];
    const float* hh_vs    = (const float*)d_in[8];
    const float* inv_freq = (const float*)d_in[9];
    const float* rope_pos = (const float*)d_in[10];
    float* out = (float*)d_out;

    float *xn, *qkv, *o_, *oproj, *gl, *x_, *x12, *ffnin, *Qm, *wf;
    cudaGetSymbolAddress((void**)&xn,    g_xn);
    cudaGetSymbolAddress((void**)&qkv,   g_qkv);
    cudaGetSymbolAddress((void**)&o_,    g_o);
    cudaGetSymbolAddress((void**)&oproj, g_oproj);
    cudaGetSymbolAddress((void**)&gl,    g_gl);
    cudaGetSymbolAddress((void**)&x_,    g_x);
    cudaGetSymbolAddress((void**)&x12,   g_x12);
    cudaGetSymbolAddress((void**)&ffnin, g_ffnin);
    cudaGetSymbolAddress((void**)&Qm,    g_Q);
    cudaGetSymbolAddress((void**)&wf,    g_w);

    static bool attr_set = false;
    if (!attr_set) {
        cudaFuncSetAttribute(flash_k, cudaFuncAttributeMaxDynamicSharedMemorySize, 65536);
        attr_set = true;
    }

    rmsnorm_k<<<MM, 256>>>(x, xn);
    hh_k<<<1, 256>>>(hh_vs, Qm);
    foldw_k<<<3*DD, 256>>>(qkv_w, Qm, wf);
    sgemm128_k<<<dim3((3*DD)/128, MM/128), 256>>>(xn, wf, qkv, MM, 3*DD, DD, nullptr, nullptr);
    rope_k<<<(MM*1024)/256, 256>>>(qkv, inv_freq, rope_pos);
    flash_k<<<dim3(SS/64, BB*HH), 256, 65536>>>(qkv, o_);
    sgemm128_k<<<dim3(DD/128, MM/128), 256>>>(o_, out_w, oproj, MM, DD, DD, nullptr, nullptr);
    sgemm128_k<<<dim3(DD/128, MM/128), 256>>>(oproj, gate_w, gl, MM, DD, DD, gate_b, nullptr);
    gate_res_k<<<(MM*DD/4 + 255)/256, 256>>>(x, oproj, gl, x_, MM*DD/4);
    rmsnorm_k<<<MM, 256>>>(x_, xn);
    sgemm128_k<<<dim3((2*FFN)/128, MM/128), 256>>>(xn, w12, x12, MM, 2*FFN, DD, nullptr, nullptr);
    swiglu_k<<<(MM*FFN/4 + 255)/256, 256>>>(x12, ffnin, MM*FFN/4);
    sgemm128_k<<<dim3(DD/128, MM/128), 256>>>(ffnin, w3, out, MM, DD, FFN, nullptr, x_);
}

// round 3
// speedup vs baseline: 9.5778x; 1.8439x over previous
#include <cuda_runtime.h>
#include <cuda_bf16.h>
#include <math.h>
#include <stdint.h>

// Problem constants
#define BB 2
#define SS 2048
#define DD 1024
#define HH 16
#define HD 64
#define FFN 4096
#define MM (BB*SS)          // 4096 rows
#define EPS_RMS 1.1920929e-07f

// ---------------- scratch (device globals; allocation-free) ----------------
static __device__ float g_xn   [MM*DD];
static __device__ float g_qkv  [MM*3*DD];
static __device__ float g_o    [MM*DD];
static __device__ float g_oproj[MM*DD];
static __device__ float g_gl   [MM*DD];
static __device__ float g_x    [MM*DD];
static __device__ float g_x12  [MM*2*FFN];
static __device__ float g_ffnin[MM*FFN];
static __device__ float g_Q    [HD*HD];
static __device__ float g_w    [3*DD*DD];      // folded qkv weights

// ---------------- helpers ----------------
__device__ __forceinline__ float tf32r(float x) {
    float y;
    asm("cvt.rna.tf32.f32 %0, %1;" : "=f"(y) : "f"(x));
    return y;
}

__device__ __forceinline__ void mma_tf32(float c[4], uint32_t a0, uint32_t a1,
                                         uint32_t a2, uint32_t a3,
                                         uint32_t b0, uint32_t b1) {
    asm volatile(
        "mma.sync.aligned.m16n8k8.row.col.f32.tf32.tf32.f32 "
        "{%0,%1,%2,%3},{%4,%5,%6,%7},{%8,%9},{%0,%1,%2,%3};\n"
        : "+f"(c[0]), "+f"(c[1]), "+f"(c[2]), "+f"(c[3])
        : "r"(a0), "r"(a1), "r"(a2), "r"(a3), "r"(b0), "r"(b1));
}

// ---------------- rmsnorm ----------------
__global__ void rmsnorm_k(const float* __restrict__ x, float* __restrict__ y) {
    int row = blockIdx.x;
    const float4* xr = (const float4*)(x + (size_t)row * DD);
    float4* yr = (float4*)(y + (size_t)row * DD);
    int tid = threadIdx.x;
    float4 v = xr[tid];
    float s = v.x*v.x + v.y*v.y + v.z*v.z + v.w*v.w;
    #pragma unroll
    for (int w = 16; w > 0; w >>= 1) s += __shfl_xor_sync(0xffffffffu, s, w);
    __shared__ float red[8];
    __shared__ float tot;
    if ((tid & 31) == 0) red[tid >> 5] = s;
    __syncthreads();
    if (tid == 0) {
        float t = 0.f;
        #pragma unroll
        for (int i = 0; i < 8; i++) t += red[i];
        tot = t;
    }
    __syncthreads();
    float r = rsqrtf(tot / (float)DD + EPS_RMS);
    yr[tid] = make_float4(v.x*r, v.y*r, v.z*r, v.w*r);
}

// ---------------- Householder product ----------------
__global__ void hh_k(const float* __restrict__ vs, float* __restrict__ Qout) {
    __shared__ float Q[HD][HD];
    __shared__ float v[HD];
    __shared__ float w[HD];
    __shared__ float cs;
    int tid = threadIdx.x;
    for (int idx = tid; idx < HD*HD; idx += 256)
        Q[idx / HD][idx % HD] = (idx / HD == idx % HD) ? 1.f : 0.f;
    __syncthreads();
    for (int r = 0; r < HD/2; r++) {
        if (tid < HD) v[tid] = vs[r*HD + tid];
        __syncthreads();
        if (tid == 0) {
            float n = 0.f;
            for (int i = 0; i < HD; i++) n += v[i]*v[i];
            cs = 2.f / (n + 1e-8f);
        }
        __syncthreads();
        if (tid < HD) {
            float s = 0.f;
            for (int i = 0; i < HD; i++) s += v[i] * Q[i][tid];
            w[tid] = s;
        }
        __syncthreads();
        for (int idx = tid; idx < HD*HD; idx += 256) {
            int i = idx / HD, j = idx % HD;
            Q[i][j] -= cs * v[i] * w[j];
        }
        __syncthreads();
    }
    for (int idx = tid; idx < HD*HD; idx += 256)
        Qout[idx] = Q[idx / HD][idx % HD];
}

// ---------------- fold Q into q,k weight rows ----------------
__global__ void foldw_k(const float* __restrict__ W, const float* __restrict__ Qm,
                        float* __restrict__ Wout) {
    int row = blockIdx.x;       // 0..3071
    int tid = threadIdx.x;
    __shared__ float coef[HD];
    bool xform = row < 2*DD;
    if (xform && tid < HD) coef[tid] = Qm[(row & 63)*HD + tid];
    __syncthreads();
    float4 acc;
    if (!xform) {
        acc = *(const float4*)(W + (size_t)row*DD + tid*4);
    } else {
        acc = make_float4(0.f, 0.f, 0.f, 0.f);
        int base = row & ~63;
        #pragma unroll 4
        for (int j = 0; j < HD; j++) {
            float cf = coef[j];
            float4 w = *(const float4*)(W + (size_t)(base + j)*DD + tid*4);
            acc.x += cf*w.x; acc.y += cf*w.y; acc.z += cf*w.z; acc.w += cf*w.w;
        }
    }
    *(float4*)(Wout + (size_t)row*DD + tid*4) = acc;
}

// ---------------- elementwise rope on q,k (q pre-scaled by 1/8) ----------------
__global__ void rope_k(float* __restrict__ qkv, const float* __restrict__ inv_freq,
                       const float* __restrict__ rope_pos) {
    int idx = blockIdx.x * 256 + threadIdx.x;
    int dp = idx & 31;
    int ph = (idx >> 5) & 31;
    int bs = idx >> 10;
    int s  = bs & (SS-1);
    float pos = rope_pos[2*s];
    float ang = pos * inv_freq[dp & 15];
    float c, sn;
    sincosf(ang, &sn, &c);
    size_t base = (size_t)bs*(3*DD) + (size_t)(ph>>4)*DD + (size_t)(ph&15)*HD;
    float t1 = qkv[base + dp], t2 = qkv[base + dp + 32];
    float o1 = t1*c - t2*sn;
    float o2 = t2*c + t1*sn;
    if (ph < 16) { o1 *= 0.125f; o2 *= 0.125f; }
    qkv[base + dp] = o1;
    qkv[base + dp + 32] = o2;
}

// ---------------- tf32 tensor-core GEMM: C = A @ W^T (+bias)(+resid) ----------------
// Block 128x128, BK=32. 8 warps as 2(m) x 4(n), warp tile 64x32.
__global__ void __launch_bounds__(256) tgemm_k(
        const float* __restrict__ A, const float* __restrict__ W,
        float* __restrict__ C, int M, int N, int K,
        const float* __restrict__ bias, const float* __restrict__ resid) {
    __shared__ __align__(16) float As[128][36];
    __shared__ __align__(16) float Bs[128][36];
    int tid = threadIdx.x;
    int lane = tid & 31, wid = tid >> 5;
    int wm = wid >> 2, wn = wid & 3;
    int g = lane >> 2, c = lane & 3;
    int m0 = blockIdx.y * 128, n0 = blockIdx.x * 128;
    float acc[4][4][4] = {};
    for (int k0 = 0; k0 < K; k0 += 32) {
        #pragma unroll
        for (int it = 0; it < 4; it++) {
            int idx = tid + it*256;
            int r = idx >> 3, c4 = idx & 7;
            float4 a = *(const float4*)(A + (size_t)(m0+r)*K + k0 + c4*4);
            a.x=tf32r(a.x); a.y=tf32r(a.y); a.z=tf32r(a.z); a.w=tf32r(a.w);
            *(float4*)&As[r][c4*4] = a;
            float4 b = *(const float4*)(W + (size_t)(n0+r)*K + k0 + c4*4);
            b.x=tf32r(b.x); b.y=tf32r(b.y); b.z=tf32r(b.z); b.w=tf32r(b.w);
            *(float4*)&Bs[r][c4*4] = b;
        }
        __syncthreads();
        #pragma unroll
        for (int ks = 0; ks < 4; ks++) {
            int kk = ks*8;
            uint32_t af[4][4], bf[4][2];
            #pragma unroll
            for (int mf = 0; mf < 4; mf++) {
                int rb = wm*64 + mf*16;
                af[mf][0] = __float_as_uint(As[rb + g    ][kk + c    ]);
                af[mf][1] = __float_as_uint(As[rb + g + 8][kk + c    ]);
                af[mf][2] = __float_as_uint(As[rb + g    ][kk + c + 4]);
                af[mf][3] = __float_as_uint(As[rb + g + 8][kk + c + 4]);
            }
            #pragma unroll
            for (int nf = 0; nf < 4; nf++) {
                int cb = wn*32 + nf*8;
                bf[nf][0] = __float_as_uint(Bs[cb + g][kk + c    ]);
                bf[nf][1] = __float_as_uint(Bs[cb + g][kk + c + 4]);
            }
            #pragma unroll
            for (int mf = 0; mf < 4; mf++)
                #pragma unroll
                for (int nf = 0; nf < 4; nf++)
                    mma_tf32(acc[mf][nf], af[mf][0], af[mf][1], af[mf][2], af[mf][3],
                             bf[nf][0], bf[nf][1]);
        }
        __syncthreads();
    }
    // epilogue
    #pragma unroll
    for (int mf = 0; mf < 4; mf++) {
        int r0 = m0 + wm*64 + mf*16 + g;
        #pragma unroll
        for (int nf = 0; nf < 4; nf++) {
            int col = n0 + wn*32 + nf*8 + 2*c;
            float2 v0 = make_float2(acc[mf][nf][0], acc[mf][nf][1]);
            float2 v1 = make_float2(acc[mf][nf][2], acc[mf][nf][3]);
            if (bias) {
                float2 bv = *(const float2*)(bias + col);
                v0.x += bv.x; v0.y += bv.y;
                v1.x += bv.x; v1.y += bv.y;
            }
            if (resid) {
                float2 r0v = *(const float2*)(resid + (size_t)r0*N + col);
                float2 r1v = *(const float2*)(resid + (size_t)(r0+8)*N + col);
                v0.x += r0v.x; v0.y += r0v.y;
                v1.x += r1v.x; v1.y += r1v.y;
            }
            *(float2*)(C + (size_t)r0*N + col) = v0;
            *(float2*)(C + (size_t)(r0+8)*N + col) = v1;
        }
    }
}

// ---------------- tensor-core flash attention ----------------
// 128 queries per block, 64x64 KV tiles, tf32 mma for S=QK^T and O+=P@V.
// smem: Ps [128][68] (Q staging + P), Ks [64][68], Vs [64][72]
#define PS_STR 68
#define KS_STR 68
#define VS_STR 72
#define SMEM_FLASH ((128*PS_STR + 64*KS_STR + 64*VS_STR) * 4)

__global__ void __launch_bounds__(256) flashm_k(const float* __restrict__ qkv,
                                                float* __restrict__ o) {
    extern __shared__ float sm[];
    float* Ps = sm;
    float* Ks = sm + 128*PS_STR;
    float* Vs = sm + 128*PS_STR + 64*KS_STR;
    int tid = threadIdx.x;
    int lane = tid & 31, wid = tid >> 5;
    int g = lane >> 2, c = lane & 3;
    int qt = (int)gridDim.x - 1 - (int)blockIdx.x;   // longest first
    int q0 = qt * 128;
    int b = blockIdx.y >> 4, h = blockIdx.y & 15;
    size_t tok0 = (size_t)b * SS;

    // stage Q (128x64) into Ps, tf32-rounded
    #pragma unroll
    for (int it = 0; it < 8; it++) {
        int idx = tid + it*256;
        int r = idx >> 4, d4 = idx & 15;
        float4 v = *(const float4*)(qkv + (tok0 + q0 + r)*(size_t)(3*DD) + h*HD + d4*4);
        v.x=tf32r(v.x); v.y=tf32r(v.y); v.z=tf32r(v.z); v.w=tf32r(v.w);
        *(float4*)(Ps + r*PS_STR + d4*4) = v;
    }
    __syncthreads();
    // Q fragments: this warp owns rows [wid*16, wid*16+16)
    int qrow = q0 + wid*16;
    uint32_t qf[8][4];
    {
        const float* base = Ps + (wid*16)*PS_STR;
        #pragma unroll
        for (int ks = 0; ks < 8; ks++) {
            int kk = ks*8;
            qf[ks][0] = __float_as_uint(base[(g    )*PS_STR + kk + c    ]);
            qf[ks][1] = __float_as_uint(base[(g + 8)*PS_STR + kk + c    ]);
            qf[ks][2] = __float_as_uint(base[(g    )*PS_STR + kk + c + 4]);
            qf[ks][3] = __float_as_uint(base[(g + 8)*PS_STR + kk + c + 4]);
        }
    }
    float oacc[8][4];
    #pragma unroll
    for (int nf = 0; nf < 8; nf++)
        #pragma unroll
        for (int i = 0; i < 4; i++) oacc[nf][i] = 0.f;
    float m0r = -1e30f, m1r = -1e30f, l0r = 0.f, l1r = 0.f;

    int jmax = 2*qt + 1;
    for (int jt = 0; jt <= jmax; jt++) {
        int j0 = jt * 64;
        __syncthreads();   // protects Ks/Vs (and Ps on iter 0)
        #pragma unroll
        for (int it = 0; it < 4; it++) {
            int idx = tid + it*256;
            int r = idx >> 4, d4 = idx & 15;
            size_t ga = (tok0 + j0 + r)*(size_t)(3*DD) + h*HD + d4*4;
            float4 kv = *(const float4*)(qkv + ga + DD);
            kv.x=tf32r(kv.x); kv.y=tf32r(kv.y); kv.z=tf32r(kv.z); kv.w=tf32r(kv.w);
            *(float4*)(Ks + r*KS_STR + d4*4) = kv;
            float4 vv = *(const float4*)(qkv + ga + 2*DD);
            vv.x=tf32r(vv.x); vv.y=tf32r(vv.y); vv.z=tf32r(vv.z); vv.w=tf32r(vv.w);
            *(float4*)(Vs + r*VS_STR + d4*4) = vv;
        }
        __syncthreads();
        if (j0 <= qrow + 15) {   // warp has unmasked work in this tile
            // S = Q K^T  (16 x 64 per warp)
            float sacc[8][4];
            #pragma unroll
            for (int nf = 0; nf < 8; nf++)
                #pragma unroll
                for (int i = 0; i < 4; i++) sacc[nf][i] = 0.f;
            #pragma unroll
            for (int ks = 0; ks < 8; ks++) {
                int kk = ks*8;
                #pragma unroll
                for (int nf = 0; nf < 8; nf++) {
                    uint32_t b0 = __float_as_uint(Ks[(nf*8 + g)*KS_STR + kk + c    ]);
                    uint32_t b1 = __float_as_uint(Ks[(nf*8 + g)*KS_STR + kk + c + 4]);
                    mma_tf32(sacc[nf], qf[ks][0], qf[ks][1], qf[ks][2], qf[ks][3], b0, b1);
                }
            }
            // causal mask (only near the diagonal)
            if (j0 + 63 > qrow) {
                #pragma unroll
                for (int nf = 0; nf < 8; nf++) {
                    int col = j0 + nf*8 + 2*c;
                    if (col     > qrow + g)     sacc[nf][0] = -1e30f;
                    if (col + 1 > qrow + g)     sacc[nf][1] = -1e30f;
                    if (col     > qrow + 8 + g) sacc[nf][2] = -1e30f;
                    if (col + 1 > qrow + 8 + g) sacc[nf][3] = -1e30f;
                }
            }
            // online softmax (rows live in 4 lanes sharing g)
            float mx0 = -1e30f, mx1 = -1e30f;
            #pragma unroll
            for (int nf = 0; nf < 8; nf++) {
                mx0 = fmaxf(mx0, fmaxf(sacc[nf][0], sacc[nf][1]));
                mx1 = fmaxf(mx1, fmaxf(sacc[nf][2], sacc[nf][3]));
            }
            mx0 = fmaxf(mx0, __shfl_xor_sync(0xffffffffu, mx0, 1));
            mx0 = fmaxf(mx0, __shfl_xor_sync(0xffffffffu, mx0, 2));
            mx1 = fmaxf(mx1, __shfl_xor_sync(0xffffffffu, mx1, 1));
            mx1 = fmaxf(mx1, __shfl_xor_sync(0xffffffffu, mx1, 2));
            float nm0 = fmaxf(m0r, mx0), nm1 = fmaxf(m1r, mx1);
            float al0 = __expf(m0r - nm0), al1 = __expf(m1r - nm1);
            float sum0 = 0.f, sum1 = 0.f;
            #pragma unroll
            for (int nf = 0; nf < 8; nf++) {
                float p0 = __expf(sacc[nf][0] - nm0);
                float p1 = __expf(sacc[nf][1] - nm0);
                float p2 = __expf(sacc[nf][2] - nm1);
                float p3 = __expf(sacc[nf][3] - nm1);
                sacc[nf][0] = p0; sacc[nf][1] = p1; sacc[nf][2] = p2; sacc[nf][3] = p3;
                sum0 += p0 + p1; sum1 += p2 + p3;
            }
            sum0 += __shfl_xor_sync(0xffffffffu, sum0, 1);
            sum0 += __shfl_xor_sync(0xffffffffu, sum0, 2);
            sum1 += __shfl_xor_sync(0xffffffffu, sum1, 1);
            sum1 += __shfl_xor_sync(0xffffffffu, sum1, 2);
            l0r = l0r*al0 + sum0; l1r = l1r*al1 + sum1;
            m0r = nm0; m1r = nm1;
            // write P to warp-local Ps rows (tf32-rounded)
            int prow = wid*16;
            #pragma unroll
            for (int nf = 0; nf < 8; nf++) {
                int col = nf*8 + 2*c;
                *(float2*)(Ps + (prow + g    )*PS_STR + col) =
                    make_float2(tf32r(sacc[nf][0]), tf32r(sacc[nf][1]));
                *(float2*)(Ps + (prow + 8 + g)*PS_STR + col) =
                    make_float2(tf32r(sacc[nf][2]), tf32r(sacc[nf][3]));
            }
            __syncwarp();
            // rescale O
            #pragma unroll
            for (int nf = 0; nf < 8; nf++) {
                oacc[nf][0] *= al0; oacc[nf][1] *= al0;
                oacc[nf][2] *= al1; oacc[nf][3] *= al1;
            }
            // O += P @ V
            #pragma unroll
            for (int ks = 0; ks < 8; ks++) {
                int kk = ks*8;
                uint32_t a0 = __float_as_uint(Ps[(prow + g    )*PS_STR + kk + c    ]);
                uint32_t a1 = __float_as_uint(Ps[(prow + 8 + g)*PS_STR + kk + c    ]);
                uint32_t a2 = __float_as_uint(Ps[(prow + g    )*PS_STR + kk + c + 4]);
                uint32_t a3 = __float_as_uint(Ps[(prow + 8 + g)*PS_STR + kk + c + 4]);
                #pragma unroll
                for (int nf = 0; nf < 8; nf++) {
                    uint32_t b0 = __float_as_uint(Vs[(kk + c    )*VS_STR + nf*8 + g]);
                    uint32_t b1 = __float_as_uint(Vs[(kk + c + 4)*VS_STR + nf*8 + g]);
                    mma_tf32(oacc[nf], a0, a1, a2, a3, b0, b1);
                }
            }
        }
    }
    // epilogue
    float inv0 = 1.f / l0r, inv1 = 1.f / l1r;
    #pragma unroll
    for (int nf = 0; nf < 8; nf++) {
        int col = h*HD + nf*8 + 2*c;
        size_t r0 = (tok0 + qrow + g    )*(size_t)DD + col;
        size_t r1 = (tok0 + qrow + 8 + g)*(size_t)DD + col;
        *(float2*)(o + r0) = make_float2(oacc[nf][0]*inv0, oacc[nf][1]*inv0);
        *(float2*)(o + r1) = make_float2(oacc[nf][2]*inv1, oacc[nf][3]*inv1);
    }
}

// ---------------- x = resid + oproj * sigmoid(gl) ----------------
__global__ void gate_res_k(const float* __restrict__ resid, const float* __restrict__ oproj,
                           const float* __restrict__ gl, float* __restrict__ xout, int n4) {
    int i = blockIdx.x * blockDim.x + threadIdx.x;
    if (i >= n4) return;
    float4 r = ((const float4*)resid)[i];
    float4 p = ((const float4*)oproj)[i];
    float4 gv = ((const float4*)gl)[i];
    float4 o;
    o.x = r.x + p.x / (1.f + __expf(-gv.x));
    o.y = r.y + p.y / (1.f + __expf(-gv.y));
    o.z = r.z + p.z / (1.f + __expf(-gv.z));
    o.w = r.w + p.w / (1.f + __expf(-gv.w));
    ((float4*)xout)[i] = o;
}

// ---------------- ffnin = silu(x1) * x2 ----------------
__global__ void swiglu_k(const float* __restrict__ x12, float* __restrict__ ffnin, int n4) {
    int i = blockIdx.x * blockDim.x + threadIdx.x;
    if (i >= n4) return;
    int m = i >> 10;
    int j4 = i & 1023;
    float4 a = ((const float4*)x12)[(size_t)m*2048 + j4];
    float4 b = ((const float4*)x12)[(size_t)m*2048 + 1024 + j4];
    float4 o;
    o.x = (a.x / (1.f + __expf(-a.x))) * b.x;
    o.y = (a.y / (1.f + __expf(-a.y))) * b.y;
    o.z = (a.z / (1.f + __expf(-a.z))) * b.z;
    o.w = (a.w / (1.f + __expf(-a.w))) * b.w;
    ((float4*)ffnin)[i] = o;
}

// ---------------- launch ----------------
extern "C" void kernel_launch(void* const* d_in, const int* in_sizes, int n_in,
                              void* d_out, int out_size) {
    const float* x        = (const float*)d_in[0];
    const float* qkv_w    = (const float*)d_in[2];
    const float* out_w    = (const float*)d_in[3];
    const float* gate_w   = (const float*)d_in[4];
    const float* gate_b   = (const float*)d_in[5];
    const float* w12      = (const float*)d_in[6];
    const float* w3       = (const float*)d_in[7];
    const float* hh_vs    = (const float*)d_in[8];
    const float* inv_freq = (const float*)d_in[9];
    const float* rope_pos = (const float*)d_in[10];
    float* out = (float*)d_out;

    float *xn, *qkv, *o_, *oproj, *gl, *x_, *x12, *ffnin, *Qm, *wf;
    cudaGetSymbolAddress((void**)&xn,    g_xn);
    cudaGetSymbolAddress((void**)&qkv,   g_qkv);
    cudaGetSymbolAddress((void**)&o_,    g_o);
    cudaGetSymbolAddress((void**)&oproj, g_oproj);
    cudaGetSymbolAddress((void**)&gl,    g_gl);
    cudaGetSymbolAddress((void**)&x_,    g_x);
    cudaGetSymbolAddress((void**)&x12,   g_x12);
    cudaGetSymbolAddress((void**)&ffnin, g_ffnin);
    cudaGetSymbolAddress((void**)&Qm,    g_Q);
    cudaGetSymbolAddress((void**)&wf,    g_w);

    static bool attr_set = false;
    if (!attr_set) {
        cudaFuncSetAttribute(flashm_k, cudaFuncAttributeMaxDynamicSharedMemorySize, SMEM_FLASH);
        attr_set = true;
    }

    rmsnorm_k<<<MM, 256>>>(x, xn);
    hh_k<<<1, 256>>>(hh_vs, Qm);
    foldw_k<<<3*DD, 256>>>(qkv_w, Qm, wf);
    tgemm_k<<<dim3((3*DD)/128, MM/128), 256>>>(xn, wf, qkv, MM, 3*DD, DD, nullptr, nullptr);
    rope_k<<<(MM*1024)/256, 256>>>(qkv, inv_freq, rope_pos);
    flashm_k<<<dim3(SS/128, BB*HH), 256, SMEM_FLASH>>>(qkv, o_);
    tgemm_k<<<dim3(DD/128, MM/128), 256>>>(o_, out_w, oproj, MM, DD, DD, nullptr, nullptr);
    tgemm_k<<<dim3(DD/128, MM/128), 256>>>(oproj, gate_w, gl, MM, DD, DD, gate_b, nullptr);
    gate_res_k<<<(MM*DD/4 + 255)/256, 256>>>(x, oproj, gl, x_, MM*DD/4);
    rmsnorm_k<<<MM, 256>>>(x_, xn);
    tgemm_k<<<dim3((2*FFN)/128, MM/128), 256>>>(xn, w12, x12, MM, 2*FFN, DD, nullptr, nullptr);
    swiglu_k<<<(MM*FFN/4 + 255)/256, 256>>>(x12, ffnin, MM*FFN/4);
    tgemm_k<<<dim3(DD/128, MM/128), 256>>>(ffnin, w3, out, MM, DD, FFN, nullptr, x_);
}

// round 4
// speedup vs baseline: 15.6887x; 1.6380x over previous
#include <cuda_runtime.h>
#include <cuda_bf16.h>
#include <math.h>
#include <stdint.h>

// Problem constants
#define BB 2
#define SS 2048
#define DD 1024
#define HH 16
#define HD 64
#define FFN 4096
#define MM (BB*SS)          // 4096 rows
#define EPS_RMS 1.1920929e-07f

// ---------------- scratch (device globals; allocation-free) ----------------
static __device__ float g_xn   [MM*DD];
static __device__ float g_qkv  [MM*3*DD];
static __device__ float g_o    [MM*DD];
static __device__ float g_oproj[MM*DD];
static __device__ float g_x    [MM*DD];
static __device__ float g_x12  [MM*2*FFN];
static __device__ float g_ffnin[MM*FFN];
static __device__ float g_Q    [HD*HD];
static __device__ float g_w    [3*DD*DD];      // folded qkv weights

// ---------------- helpers ----------------
__device__ __forceinline__ void mma_tf32(float c[4], uint32_t a0, uint32_t a1,
                                         uint32_t a2, uint32_t a3,
                                         uint32_t b0, uint32_t b1) {
    asm volatile(
        "mma.sync.aligned.m16n8k8.row.col.f32.tf32.tf32.f32 "
        "{%0,%1,%2,%3},{%4,%5,%6,%7},{%8,%9},{%0,%1,%2,%3};\n"
        : "+f"(c[0]), "+f"(c[1]), "+f"(c[2]), "+f"(c[3])
        : "r"(a0), "r"(a1), "r"(a2), "r"(a3), "r"(b0), "r"(b1));
}
__device__ __forceinline__ void cp16(uint32_t saddr, const void* gptr) {
    asm volatile("cp.async.cg.shared.global [%0], [%1], 16;\n" :: "r"(saddr), "l"(gptr));
}
#define CP_COMMIT() asm volatile("cp.async.commit_group;\n")
#define CP_WAIT1()  asm volatile("cp.async.wait_group 1;\n")
#define CP_WAIT0()  asm volatile("cp.async.wait_group 0;\n")

// ---------------- rmsnorm ----------------
__global__ void rmsnorm_k(const float* __restrict__ x, float* __restrict__ y) {
    int row = blockIdx.x;
    const float4* xr = (const float4*)(x + (size_t)row * DD);
    float4* yr = (float4*)(y + (size_t)row * DD);
    int tid = threadIdx.x;
    float4 v = xr[tid];
    float s = v.x*v.x + v.y*v.y + v.z*v.z + v.w*v.w;
    #pragma unroll
    for (int w = 16; w > 0; w >>= 1) s += __shfl_xor_sync(0xffffffffu, s, w);
    __shared__ float red[8];
    __shared__ float tot;
    if ((tid & 31) == 0) red[tid >> 5] = s;
    __syncthreads();
    if (tid == 0) {
        float t = 0.f;
        #pragma unroll
        for (int i = 0; i < 8; i++) t += red[i];
        tot = t;
    }
    __syncthreads();
    float r = rsqrtf(tot / (float)DD + EPS_RMS);
    yr[tid] = make_float4(v.x*r, v.y*r, v.z*r, v.w*r);
}

// ---------------- Householder product ----------------
__global__ void hh_k(const float* __restrict__ vs, float* __restrict__ Qout) {
    __shared__ float Q[HD][HD];
    __shared__ float v[HD];
    __shared__ float w[HD];
    __shared__ float cs;
    int tid = threadIdx.x;
    for (int idx = tid; idx < HD*HD; idx += 256)
        Q[idx / HD][idx % HD] = (idx / HD == idx % HD) ? 1.f : 0.f;
    __syncthreads();
    for (int r = 0; r < HD/2; r++) {
        if (tid < HD) v[tid] = vs[r*HD + tid];
        __syncthreads();
        if (tid == 0) {
            float n = 0.f;
            for (int i = 0; i < HD; i++) n += v[i]*v[i];
            cs = 2.f / (n + 1e-8f);
        }
        __syncthreads();
        if (tid < HD) {
            float s = 0.f;
            for (int i = 0; i < HD; i++) s += v[i] * Q[i][tid];
            w[tid] = s;
        }
        __syncthreads();
        for (int idx = tid; idx < HD*HD; idx += 256) {
            int i = idx / HD, j = idx % HD;
            Q[i][j] -= cs * v[i] * w[j];
        }
        __syncthreads();
    }
    for (int idx = tid; idx < HD*HD; idx += 256)
        Qout[idx] = Q[idx / HD][idx % HD];
}

// ---------------- fold Q into q,k weight rows ----------------
__global__ void foldw_k(const float* __restrict__ W, const float* __restrict__ Qm,
                        float* __restrict__ Wout) {
    int row = blockIdx.x;       // 0..3071
    int tid = threadIdx.x;
    __shared__ float coef[HD];
    bool xform = row < 2*DD;
    if (xform && tid < HD) coef[tid] = Qm[(row & 63)*HD + tid];
    __syncthreads();
    float4 acc;
    if (!xform) {
        acc = *(const float4*)(W + (size_t)row*DD + tid*4);
    } else {
        acc = make_float4(0.f, 0.f, 0.f, 0.f);
        int base = row & ~63;
        #pragma unroll 4
        for (int j = 0; j < HD; j++) {
            float cf = coef[j];
            float4 w = *(const float4*)(W + (size_t)(base + j)*DD + tid*4);
            acc.x += cf*w.x; acc.y += cf*w.y; acc.z += cf*w.z; acc.w += cf*w.w;
        }
    }
    *(float4*)(Wout + (size_t)row*DD + tid*4) = acc;
}

// ---------------- elementwise rope on q,k (q pre-scaled by 1/8) ----------------
__global__ void rope_k(float* __restrict__ qkv, const float* __restrict__ inv_freq,
                       const float* __restrict__ rope_pos) {
    int idx = blockIdx.x * 256 + threadIdx.x;
    int dp = idx & 31;
    int ph = (idx >> 5) & 31;
    int bs = idx >> 10;
    int s  = bs & (SS-1);
    float pos = rope_pos[2*s];
    float ang = pos * inv_freq[dp & 15];
    float c, sn;
    sincosf(ang, &sn, &c);
    size_t base = (size_t)bs*(3*DD) + (size_t)(ph>>4)*DD + (size_t)(ph&15)*HD;
    float t1 = qkv[base + dp], t2 = qkv[base + dp + 32];
    float o1 = t1*c - t2*sn;
    float o2 = t2*c + t1*sn;
    if (ph < 16) { o1 *= 0.125f; o2 *= 0.125f; }
    qkv[base + dp] = o1;
    qkv[base + dp + 32] = o2;
}

// ---------------- tf32 tensor-core GEMM, cp.async double-buffered ----------------
// Block 128x128, BK=32, 8 warps 2(m)x4(n), warp tile 64x32.
// Epilogue modes: +bias, +resid, or gate fusion (C = resid + gatein*sigmoid(acc+bias)).
#define TG_SMEM (2 * 2 * 128 * 36 * 4)   // 73728 bytes
__global__ void __launch_bounds__(256) tgemm_k(
        const float* __restrict__ A, const float* __restrict__ W,
        float* __restrict__ C, int M, int N, int K,
        const float* __restrict__ bias, const float* __restrict__ resid,
        const float* __restrict__ gatein) {
    extern __shared__ float sm[];
    float* As = sm;                 // [2][128][36]
    float* Bs = sm + 2*128*36;      // [2][128][36]
    uint32_t as_u32 = (uint32_t)__cvta_generic_to_shared(As);
    uint32_t bs_u32 = (uint32_t)__cvta_generic_to_shared(Bs);
    int tid = threadIdx.x;
    int lane = tid & 31, wid = tid >> 5;
    int wm = wid >> 2, wn = wid & 3;
    int g = lane >> 2, c = lane & 3;
    int m0 = blockIdx.y * 128, n0 = blockIdx.x * 128;
    int pr = tid >> 3, pc = tid & 7;     // producer: 32 rows/pass, 8 float4 cols

    float acc[4][4][4] = {};
    int nIter = K >> 5;

    // prologue: stage 0
    #pragma unroll
    for (int p = 0; p < 4; p++) {
        int row = p*32 + pr;
        cp16(as_u32 + (row*36 + pc*4)*4, A + (size_t)(m0+row)*K + pc*4);
        cp16(bs_u32 + (row*36 + pc*4)*4, W + (size_t)(n0+row)*K + pc*4);
    }
    CP_COMMIT();

    for (int i = 0; i < nIter; i++) {
        int buf = i & 1;
        if (i + 1 < nIter) {
            int nb = (i + 1) & 1;
            int k0 = (i + 1) << 5;
            #pragma unroll
            for (int p = 0; p < 4; p++) {
                int row = p*32 + pr;
                cp16(as_u32 + ((nb*128 + row)*36 + pc*4)*4, A + (size_t)(m0+row)*K + k0 + pc*4);
                cp16(bs_u32 + ((nb*128 + row)*36 + pc*4)*4, W + (size_t)(n0+row)*K + k0 + pc*4);
            }
            CP_COMMIT();
            CP_WAIT1();
        } else {
            CP_WAIT0();
        }
        __syncthreads();
        const float* Ab = As + buf*128*36;
        const float* Bb = Bs + buf*128*36;
        #pragma unroll
        for (int ks = 0; ks < 4; ks++) {
            int kk = ks*8;
            uint32_t af[4][4], bf[4][2];
            #pragma unroll
            for (int mf = 0; mf < 4; mf++) {
                int rb = wm*64 + mf*16;
                af[mf][0] = __float_as_uint(Ab[(rb + g    )*36 + kk + c    ]);
                af[mf][1] = __float_as_uint(Ab[(rb + g + 8)*36 + kk + c    ]);
                af[mf][2] = __float_as_uint(Ab[(rb + g    )*36 + kk + c + 4]);
                af[mf][3] = __float_as_uint(Ab[(rb + g + 8)*36 + kk + c + 4]);
            }
            #pragma unroll
            for (int nf = 0; nf < 4; nf++) {
                int cb = wn*32 + nf*8;
                bf[nf][0] = __float_as_uint(Bb[(cb + g)*36 + kk + c    ]);
                bf[nf][1] = __float_as_uint(Bb[(cb + g)*36 + kk + c + 4]);
            }
            #pragma unroll
            for (int mf = 0; mf < 4; mf++)
                #pragma unroll
                for (int nf = 0; nf < 4; nf++)
                    mma_tf32(acc[mf][nf], af[mf][0], af[mf][1], af[mf][2], af[mf][3],
                             bf[nf][0], bf[nf][1]);
        }
        __syncthreads();
    }
    // epilogue
    #pragma unroll
    for (int mf = 0; mf < 4; mf++) {
        int r0 = m0 + wm*64 + mf*16 + g;
        #pragma unroll
        for (int nf = 0; nf < 4; nf++) {
            int col = n0 + wn*32 + nf*8 + 2*c;
            float v[2][2] = {{acc[mf][nf][0], acc[mf][nf][1]},
                             {acc[mf][nf][2], acc[mf][nf][3]}};
            if (bias) {
                float2 bv = *(const float2*)(bias + col);
                v[0][0]+=bv.x; v[0][1]+=bv.y; v[1][0]+=bv.x; v[1][1]+=bv.y;
            }
            if (gatein) {
                #pragma unroll
                for (int rr = 0; rr < 2; rr++) {
                    size_t off = (size_t)(r0 + 8*rr)*N + col;
                    float2 gi = *(const float2*)(gatein + off);
                    float2 rs = *(const float2*)(resid + off);
                    v[rr][0] = rs.x + gi.x / (1.f + __expf(-v[rr][0]));
                    v[rr][1] = rs.y + gi.y / (1.f + __expf(-v[rr][1]));
                }
            } else if (resid) {
                #pragma unroll
                for (int rr = 0; rr < 2; rr++) {
                    float2 rs = *(const float2*)(resid + (size_t)(r0 + 8*rr)*N + col);
                    v[rr][0] += rs.x; v[rr][1] += rs.y;
                }
            }
            *(float2*)(C + (size_t)r0*N + col)     = make_float2(v[0][0], v[0][1]);
            *(float2*)(C + (size_t)(r0+8)*N + col) = make_float2(v[1][0], v[1][1]);
        }
    }
}

// ---------------- tensor-core flash attention, cp.async double-buffered ----------------
// 128 queries/block, 64x64 KV tiles.
#define PS_STR 68
#define KS_STR 68
#define VS_STR 72
#define SMEM_FLASH ((128*PS_STR + 2*64*KS_STR + 2*64*VS_STR) * 4)

__global__ void __launch_bounds__(256) flashm_k(const float* __restrict__ qkv,
                                                float* __restrict__ o) {
    extern __shared__ float sm[];
    float* Ps = sm;
    float* Ks = sm + 128*PS_STR;
    float* Vs = Ks + 2*64*KS_STR;
    uint32_t ks_u32 = (uint32_t)__cvta_generic_to_shared(Ks);
    uint32_t vs_u32 = (uint32_t)__cvta_generic_to_shared(Vs);
    int tid = threadIdx.x;
    int lane = tid & 31, wid = tid >> 5;
    int g = lane >> 2, c = lane & 3;
    int qt = (int)gridDim.x - 1 - (int)blockIdx.x;   // longest first
    int q0 = qt * 128;
    int b = blockIdx.y >> 4, h = blockIdx.y & 15;
    size_t tok0 = (size_t)b * SS;

    // issue KV tile 0 loads
    {
        #pragma unroll
        for (int it = 0; it < 4; it++) {
            int idx = tid + it*256;
            int r = idx >> 4, d4 = idx & 15;
            const float* gk = qkv + (tok0 + r)*(size_t)(3*DD) + DD + h*HD + d4*4;
            cp16(ks_u32 + (r*KS_STR + d4*4)*4, gk);
            cp16(vs_u32 + (r*VS_STR + d4*4)*4, gk + DD);
        }
        CP_COMMIT();
    }
    // stage Q (128x64) into Ps (overlaps with tile-0 cp.async)
    #pragma unroll
    for (int it = 0; it < 8; it++) {
        int idx = tid + it*256;
        int r = idx >> 4, d4 = idx & 15;
        float4 v = *(const float4*)(qkv + (tok0 + q0 + r)*(size_t)(3*DD) + h*HD + d4*4);
        *(float4*)(Ps + r*PS_STR + d4*4) = v;
    }
    __syncthreads();
    int qrow = q0 + wid*16;
    uint32_t qf[8][4];
    {
        const float* base = Ps + (wid*16)*PS_STR;
        #pragma unroll
        for (int ks = 0; ks < 8; ks++) {
            int kk = ks*8;
            qf[ks][0] = __float_as_uint(base[(g    )*PS_STR + kk + c    ]);
            qf[ks][1] = __float_as_uint(base[(g + 8)*PS_STR + kk + c    ]);
            qf[ks][2] = __float_as_uint(base[(g    )*PS_STR + kk + c + 4]);
            qf[ks][3] = __float_as_uint(base[(g + 8)*PS_STR + kk + c + 4]);
        }
    }
    float oacc[8][4];
    #pragma unroll
    for (int nf = 0; nf < 8; nf++)
        #pragma unroll
        for (int i = 0; i < 4; i++) oacc[nf][i] = 0.f;
    float m0r = -1e30f, m1r = -1e30f, l0r = 0.f, l1r = 0.f;

    int jmax = 2*qt + 1;
    for (int jt = 0; jt <= jmax; jt++) {
        int j0 = jt * 64;
        int buf = jt & 1;
        if (jt < jmax) {
            int nb = (jt + 1) & 1;
            int nj0 = (jt + 1) * 64;
            #pragma unroll
            for (int it = 0; it < 4; it++) {
                int idx = tid + it*256;
                int r = idx >> 4, d4 = idx & 15;
                const float* gk = qkv + (tok0 + nj0 + r)*(size_t)(3*DD) + DD + h*HD + d4*4;
                cp16(ks_u32 + ((nb*64 + r)*KS_STR + d4*4)*4, gk);
                cp16(vs_u32 + ((nb*64 + r)*VS_STR + d4*4)*4, gk + DD);
            }
            CP_COMMIT();
            CP_WAIT1();
        } else {
            CP_WAIT0();
        }
        __syncthreads();
        const float* Kb = Ks + buf*64*KS_STR;
        const float* Vb = Vs + buf*64*VS_STR;
        if (j0 <= qrow + 15) {
            // S = Q K^T (16x64 per warp)
            float sacc[8][4];
            #pragma unroll
            for (int nf = 0; nf < 8; nf++)
                #pragma unroll
                for (int i = 0; i < 4; i++) sacc[nf][i] = 0.f;
            #pragma unroll
            for (int ks = 0; ks < 8; ks++) {
                int kk = ks*8;
                #pragma unroll
                for (int nf = 0; nf < 8; nf++) {
                    uint32_t b0 = __float_as_uint(Kb[(nf*8 + g)*KS_STR + kk + c    ]);
                    uint32_t b1 = __float_as_uint(Kb[(nf*8 + g)*KS_STR + kk + c + 4]);
                    mma_tf32(sacc[nf], qf[ks][0], qf[ks][1], qf[ks][2], qf[ks][3], b0, b1);
                }
            }
            // causal mask near the diagonal
            if (j0 + 63 > qrow) {
                #pragma unroll
                for (int nf = 0; nf < 8; nf++) {
                    int col = j0 + nf*8 + 2*c;
                    if (col     > qrow + g)     sacc[nf][0] = -1e30f;
                    if (col + 1 > qrow + g)     sacc[nf][1] = -1e30f;
                    if (col     > qrow + 8 + g) sacc[nf][2] = -1e30f;
                    if (col + 1 > qrow + 8 + g) sacc[nf][3] = -1e30f;
                }
            }
            // online softmax (rows in 4 lanes sharing g)
            float mx0 = -1e30f, mx1 = -1e30f;
            #pragma unroll
            for (int nf = 0; nf < 8; nf++) {
                mx0 = fmaxf(mx0, fmaxf(sacc[nf][0], sacc[nf][1]));
                mx1 = fmaxf(mx1, fmaxf(sacc[nf][2], sacc[nf][3]));
            }
            mx0 = fmaxf(mx0, __shfl_xor_sync(0xffffffffu, mx0, 1));
            mx0 = fmaxf(mx0, __shfl_xor_sync(0xffffffffu, mx0, 2));
            mx1 = fmaxf(mx1, __shfl_xor_sync(0xffffffffu, mx1, 1));
            mx1 = fmaxf(mx1, __shfl_xor_sync(0xffffffffu, mx1, 2));
            float nm0 = fmaxf(m0r, mx0), nm1 = fmaxf(m1r, mx1);
            float al0 = __expf(m0r - nm0), al1 = __expf(m1r - nm1);
            float sum0 = 0.f, sum1 = 0.f;
            #pragma unroll
            for (int nf = 0; nf < 8; nf++) {
                float p0 = __expf(sacc[nf][0] - nm0);
                float p1 = __expf(sacc[nf][1] - nm0);
                float p2 = __expf(sacc[nf][2] - nm1);
                float p3 = __expf(sacc[nf][3] - nm1);
                sacc[nf][0] = p0; sacc[nf][1] = p1; sacc[nf][2] = p2; sacc[nf][3] = p3;
                sum0 += p0 + p1; sum1 += p2 + p3;
            }
            sum0 += __shfl_xor_sync(0xffffffffu, sum0, 1);
            sum0 += __shfl_xor_sync(0xffffffffu, sum0, 2);
            sum1 += __shfl_xor_sync(0xffffffffu, sum1, 1);
            sum1 += __shfl_xor_sync(0xffffffffu, sum1, 2);
            l0r = l0r*al0 + sum0; l1r = l1r*al1 + sum1;
            m0r = nm0; m1r = nm1;
            // write P to warp-local Ps rows
            int prow = wid*16;
            #pragma unroll
            for (int nf = 0; nf < 8; nf++) {
                int col = nf*8 + 2*c;
                *(float2*)(Ps + (prow + g    )*PS_STR + col) = make_float2(sacc[nf][0], sacc[nf][1]);
                *(float2*)(Ps + (prow + 8 + g)*PS_STR + col) = make_float2(sacc[nf][2], sacc[nf][3]);
            }
            __syncwarp();
            // rescale O
            #pragma unroll
            for (int nf = 0; nf < 8; nf++) {
                oacc[nf][0] *= al0; oacc[nf][1] *= al0;
                oacc[nf][2] *= al1; oacc[nf][3] *= al1;
            }
            // O += P @ V
            #pragma unroll
            for (int ks = 0; ks < 8; ks++) {
                int kk = ks*8;
                uint32_t a0 = __float_as_uint(Ps[(prow + g    )*PS_STR + kk + c    ]);
                uint32_t a1 = __float_as_uint(Ps[(prow + 8 + g)*PS_STR + kk + c    ]);
                uint32_t a2 = __float_as_uint(Ps[(prow + g    )*PS_STR + kk + c + 4]);
                uint32_t a3 = __float_as_uint(Ps[(prow + 8 + g)*PS_STR + kk + c + 4]);
                #pragma unroll
                for (int nf = 0; nf < 8; nf++) {
                    uint32_t b0 = __float_as_uint(Vb[(kk + c    )*VS_STR + nf*8 + g]);
                    uint32_t b1 = __float_as_uint(Vb[(kk + c + 4)*VS_STR + nf*8 + g]);
                    mma_tf32(oacc[nf], a0, a1, a2, a3, b0, b1);
                }
            }
        }
        __syncthreads();
    }
    // epilogue
    float inv0 = 1.f / l0r, inv1 = 1.f / l1r;
    #pragma unroll
    for (int nf = 0; nf < 8; nf++) {
        int col = h*HD + nf*8 + 2*c;
        size_t r0 = (tok0 + qrow + g    )*(size_t)DD + col;
        size_t r1 = (tok0 + qrow + 8 + g)*(size_t)DD + col;
        *(float2*)(o + r0) = make_float2(oacc[nf][0]*inv0, oacc[nf][1]*inv0);
        *(float2*)(o + r1) = make_float2(oacc[nf][2]*inv1, oacc[nf][3]*inv1);
    }
}

// ---------------- ffnin = silu(x1) * x2 ----------------
__global__ void swiglu_k(const float* __restrict__ x12, float* __restrict__ ffnin, int n4) {
    int i = blockIdx.x * blockDim.x + threadIdx.x;
    if (i >= n4) return;
    int m = i >> 10;
    int j4 = i & 1023;
    float4 a = ((const float4*)x12)[(size_t)m*2048 + j4];
    float4 b = ((const float4*)x12)[(size_t)m*2048 + 1024 + j4];
    float4 o;
    o.x = (a.x / (1.f + __expf(-a.x))) * b.x;
    o.y = (a.y / (1.f + __expf(-a.y))) * b.y;
    o.z = (a.z / (1.f + __expf(-a.z))) * b.z;
    o.w = (a.w / (1.f + __expf(-a.w))) * b.w;
    ((float4*)ffnin)[i] = o;
}

// ---------------- launch ----------------
extern "C" void kernel_launch(void* const* d_in, const int* in_sizes, int n_in,
                              void* d_out, int out_size) {
    const float* x        = (const float*)d_in[0];
    const float* qkv_w    = (const float*)d_in[2];
    const float* out_w    = (const float*)d_in[3];
    const float* gate_w   = (const float*)d_in[4];
    const float* gate_b   = (const float*)d_in[5];
    const float* w12      = (const float*)d_in[6];
    const float* w3       = (const float*)d_in[7];
    const float* hh_vs    = (const float*)d_in[8];
    const float* inv_freq = (const float*)d_in[9];
    const float* rope_pos = (const float*)d_in[10];
    float* out = (float*)d_out;

    float *xn, *qkv, *o_, *oproj, *x_, *x12, *ffnin, *Qm, *wf;
    cudaGetSymbolAddress((void**)&xn,    g_xn);
    cudaGetSymbolAddress((void**)&qkv,   g_qkv);
    cudaGetSymbolAddress((void**)&o_,    g_o);
    cudaGetSymbolAddress((void**)&oproj, g_oproj);
    cudaGetSymbolAddress((void**)&x_,    g_x);
    cudaGetSymbolAddress((void**)&x12,   g_x12);
    cudaGetSymbolAddress((void**)&ffnin, g_ffnin);
    cudaGetSymbolAddress((void**)&Qm,    g_Q);
    cudaGetSymbolAddress((void**)&wf,    g_w);

    static bool attr_set = false;
    if (!attr_set) {
        cudaFuncSetAttribute(flashm_k, cudaFuncAttributeMaxDynamicSharedMemorySize, SMEM_FLASH);
        cudaFuncSetAttribute(tgemm_k, cudaFuncAttributeMaxDynamicSharedMemorySize, TG_SMEM);
        attr_set = true;
    }

    rmsnorm_k<<<MM, 256>>>(x, xn);
    hh_k<<<1, 256>>>(hh_vs, Qm);
    foldw_k<<<3*DD, 256>>>(qkv_w, Qm, wf);
    tgemm_k<<<dim3((3*DD)/128, MM/128), 256, TG_SMEM>>>(xn, wf, qkv, MM, 3*DD, DD,
                                                        nullptr, nullptr, nullptr);
    rope_k<<<(MM*1024)/256, 256>>>(qkv, inv_freq, rope_pos);
    flashm_k<<<dim3(SS/128, BB*HH), 256, SMEM_FLASH>>>(qkv, o_);
    tgemm_k<<<dim3(DD/128, MM/128), 256, TG_SMEM>>>(o_, out_w, oproj, MM, DD, DD,
                                                    nullptr, nullptr, nullptr);
    // gate GEMM with fused epilogue: x_ = x + oproj * sigmoid(oproj@gate_w^T + b)
    tgemm_k<<<dim3(DD/128, MM/128), 256, TG_SMEM>>>(oproj, gate_w, x_, MM, DD, DD,
                                                    gate_b, x, oproj);
    rmsnorm_k<<<MM, 256>>>(x_, xn);
    tgemm_k<<<dim3((2*FFN)/128, MM/128), 256, TG_SMEM>>>(xn, w12, x12, MM, 2*FFN, DD,
                                                         nullptr, nullptr, nullptr);
    swiglu_k<<<(MM*FFN/4 + 255)/256, 256>>>(x12, ffnin, MM*FFN/4);
    tgemm_k<<<dim3(DD/128, MM/128), 256, TG_SMEM>>>(ffnin, w3, out, MM, DD, FFN,
                                                    nullptr, x_, nullptr);
}